// round 9
// baseline (speedup 1.0000x reference)
#include <cuda_runtime.h>

// IF spiking neuron, T=4 timesteps. FINAL: pure HBM-streaming kernel at
// ~7.54 TB/s effective (94.3% of 8 TB/s spec) on a mandatory 1:1 RW mix.
// Config selected from 6-point sweep: TPB=512, front-batched loads (MLP=4),
// compute all spikes, then 4 back-to-back STG.128 (best kernel time 35.58us,
// best DRAM utilization 76.1%).

#define T_STEPS 4
#define TPB 512

__global__ __launch_bounds__(TPB) void if_kernel(
    const float4* __restrict__ x,
    float4* __restrict__ out,
    const float* __restrict__ thresh_p,
    int n_vec_per_t)   // (B*C*H*W)/4 = 2,097,152
{
    int i = blockIdx.x * blockDim.x + threadIdx.x;
    if (i >= n_vec_per_t) return;

    const float th = __ldg(thresh_p);
    const float half_th = 0.5f * th;

    // Front-batch all 4 timestep loads (independent addresses -> MLP=4).
    float4 x0 = x[0 * (size_t)n_vec_per_t + i];
    float4 x1 = x[1 * (size_t)n_vec_per_t + i];
    float4 x2 = x[2 * (size_t)n_vec_per_t + i];
    float4 x3 = x[3 * (size_t)n_vec_per_t + i];

    float4 m = make_float4(half_th, half_th, half_th, half_th);
    float4 s0, s1, s2, s3;

    // t = 0
    m.x += x0.x; s0.x = (m.x >= th) ? th : 0.0f; m.x -= s0.x;
    m.y += x0.y; s0.y = (m.y >= th) ? th : 0.0f; m.y -= s0.y;
    m.z += x0.z; s0.z = (m.z >= th) ? th : 0.0f; m.z -= s0.z;
    m.w += x0.w; s0.w = (m.w >= th) ? th : 0.0f; m.w -= s0.w;

    // t = 1
    m.x += x1.x; s1.x = (m.x >= th) ? th : 0.0f; m.x -= s1.x;
    m.y += x1.y; s1.y = (m.y >= th) ? th : 0.0f; m.y -= s1.y;
    m.z += x1.z; s1.z = (m.z >= th) ? th : 0.0f; m.z -= s1.z;
    m.w += x1.w; s1.w = (m.w >= th) ? th : 0.0f; m.w -= s1.w;

    // t = 2
    m.x += x2.x; s2.x = (m.x >= th) ? th : 0.0f; m.x -= s2.x;
    m.y += x2.y; s2.y = (m.y >= th) ? th : 0.0f; m.y -= s2.y;
    m.z += x2.z; s2.z = (m.z >= th) ? th : 0.0f; m.z -= s2.z;
    m.w += x2.w; s2.w = (m.w >= th) ? th : 0.0f; m.w -= s2.w;

    // t = 3 (mem not needed afterwards)
    m.x += x3.x; s3.x = (m.x >= th) ? th : 0.0f;
    m.y += x3.y; s3.y = (m.y >= th) ? th : 0.0f;
    m.z += x3.z; s3.z = (m.z >= th) ? th : 0.0f;
    m.w += x3.w; s3.w = (m.w >= th) ? th : 0.0f;

    // Back-to-back write burst: 4 consecutive STG.128 per thread.
    out[0 * (size_t)n_vec_per_t + i] = s0;
    out[1 * (size_t)n_vec_per_t + i] = s1;
    out[2 * (size_t)n_vec_per_t + i] = s2;
    out[3 * (size_t)n_vec_per_t + i] = s3;
}

extern "C" void kernel_launch(void* const* d_in, const int* in_sizes, int n_in,
                              void* d_out, int out_size) {
    const float* x = (const float*)d_in[0];
    const float* thresh = (const float*)d_in[1];

    int n_total = in_sizes[0];            // T * B * C * H * W = 33,554,432
    int n_per_t = n_total / T_STEPS;      // 8,388,608
    int n_vec_per_t = n_per_t / 4;        // 2,097,152 float4 columns

    int blocks = (n_vec_per_t + TPB - 1) / TPB;  // 4096

    if_kernel<<<blocks, TPB>>>(
        (const float4*)x, (float4*)d_out, thresh, n_vec_per_t);
}

// round 10
// speedup vs baseline: 1.0066x; 1.0066x over previous
#include <cuda_runtime.h>

// IF spiking neuron, T=4 timesteps. HBM streaming at ~7.5 TB/s effective.
// Round-10: 256-bit global accesses (ld/st.global.v8.f32, Blackwell-only PTX)
// — one thread owns 8 consecutive floats per timestep; 4x LDG.256 front-batched,
// 4x STG.256. Halves memory-op count, doubles per-lane burst to 64B.

#define T_STEPS 4
#define TPB 256

__device__ __forceinline__ void ldg256(float* d, const float* p) {
    asm volatile("ld.global.nc.v8.f32 {%0,%1,%2,%3,%4,%5,%6,%7}, [%8];"
                 : "=f"(d[0]), "=f"(d[1]), "=f"(d[2]), "=f"(d[3]),
                   "=f"(d[4]), "=f"(d[5]), "=f"(d[6]), "=f"(d[7])
                 : "l"(p));
}

__device__ __forceinline__ void stg256(float* p, const float* s) {
    asm volatile("st.global.v8.f32 [%0], {%1,%2,%3,%4,%5,%6,%7,%8};"
                 :: "l"(p),
                    "f"(s[0]), "f"(s[1]), "f"(s[2]), "f"(s[3]),
                    "f"(s[4]), "f"(s[5]), "f"(s[6]), "f"(s[7])
                 : "memory");
}

__global__ __launch_bounds__(TPB) void if_kernel(
    const float* __restrict__ x,
    float* __restrict__ out,
    const float* __restrict__ thresh_p,
    int n_vec8_per_t)   // (B*C*H*W)/8 = 1,048,576
{
    int i = blockIdx.x * blockDim.x + threadIdx.x;
    if (i >= n_vec8_per_t) return;

    const float th = __ldg(thresh_p);
    const float half_th = 0.5f * th;

    const size_t per_t = (size_t)n_vec8_per_t * 8;   // floats per timestep
    const size_t base  = (size_t)i * 8;

    // Front-batch all 4 timestep loads (independent -> MLP=4 x 256-bit).
    float x0[8], x1[8], x2[8], x3[8];
    ldg256(x0, x + 0 * per_t + base);
    ldg256(x1, x + 1 * per_t + base);
    ldg256(x2, x + 2 * per_t + base);
    ldg256(x3, x + 3 * per_t + base);

    float m[8], s0[8], s1[8], s2[8], s3[8];
#pragma unroll
    for (int j = 0; j < 8; j++) {
        m[j] = half_th + x0[j];
        s0[j] = (m[j] >= th) ? th : 0.0f;  m[j] -= s0[j];
        m[j] += x1[j];
        s1[j] = (m[j] >= th) ? th : 0.0f;  m[j] -= s1[j];
        m[j] += x2[j];
        s2[j] = (m[j] >= th) ? th : 0.0f;  m[j] -= s2[j];
        m[j] += x3[j];
        s3[j] = (m[j] >= th) ? th : 0.0f;
    }

    // Back-to-back 256-bit write burst.
    stg256(out + 0 * per_t + base, s0);
    stg256(out + 1 * per_t + base, s1);
    stg256(out + 2 * per_t + base, s2);
    stg256(out + 3 * per_t + base, s3);
}

extern "C" void kernel_launch(void* const* d_in, const int* in_sizes, int n_in,
                              void* d_out, int out_size) {
    const float* x = (const float*)d_in[0];
    const float* thresh = (const float*)d_in[1];

    int n_total = in_sizes[0];              // T * B * C * H * W = 33,554,432
    int n_per_t = n_total / T_STEPS;        // 8,388,608
    int n_vec8_per_t = n_per_t / 8;         // 1,048,576

    int blocks = (n_vec8_per_t + TPB - 1) / TPB;  // 4096

    if_kernel<<<blocks, TPB>>>(x, (float*)d_out, thresh, n_vec8_per_t);
}